// round 11
// baseline (speedup 1.0000x reference)
#include <cuda_runtime.h>
#include <cuda_bf16.h>
#include <math.h>
#include <stdint.h>

#define BB   32
#define SS   512
#define CC   16
#define DIN  256
#define DOUT 64

#define XPAD 264       // bf16 row stride for Xs[b][k] (528B rows, ldmatrix conflict-free)
#define WSTRIDE 68     // fp32 row stride for W stage rows (bank = 8q+ar, conflict-free)
#define KSTAGE 16      // K rows per cp.async stage
#define NSTAGES 5
#define NCHUNK 16      // 256 / 16

// Scratch (allocation-free rule: __device__ globals)
__device__ float g_uhat[(size_t)BB * SS * CC * DOUT]; // 64 MiB, [b][s][c][o]
__device__ float g_b[(size_t)BB * SS * CC];           // b_ij [b][s][c]
__device__ float g_v[(size_t)BB * CC * DOUT];         // v_j  [b][c][o] (it0 only)
__device__ float4 g_sjp[2][(size_t)8 * BB * 256];     // s_j slices [buf][w8][b][(c,o)/4]

__device__ __forceinline__ uint32_t pack_bf2(float a, float b) {
    __nv_bfloat162 t = __floats2bfloat162_rn(a, b);
    return *reinterpret_cast<uint32_t*>(&t);
}

#define MMA_BF16(d, a, b)                                                     \
    asm volatile(                                                             \
        "mma.sync.aligned.m16n8k16.row.col.f32.bf16.bf16.f32 "                \
        "{%0,%1,%2,%3},{%4,%5,%6,%7},{%8,%9},{%0,%1,%2,%3};"                  \
        : "+f"(d[0]), "+f"(d[1]), "+f"(d[2]), "+f"(d[3])                      \
        : "r"(a[0]), "r"(a[1]), "r"(a[2]), "r"(a[3]), "r"(b[0]), "r"(b[1]))

#define LDSM_X4(r0, r1, r2, r3, addr)                                         \
    asm volatile("ldmatrix.sync.aligned.m8n8.x4.shared.b16 {%0,%1,%2,%3}, [%4];" \
                 : "=r"(r0), "=r"(r1), "=r"(r2), "=r"(r3) : "r"(addr))

// ---------------------------------------------------------------------------
// GEMM: u_hat[b,s,c,o] = sum_i x[b,s,i] * W[c,s,i,o]
// grid (S, C), 128 threads, occ 4. W streamed raw fp32 via 5-stage x 16-row
// cp.async ring, ONE barrier per chunk; split-bf16 (truncation) conversion
// fused into B-fragment build; A via ldmatrix from pre-split hi/lo X tile.
// ---------------------------------------------------------------------------
__global__ void __launch_bounds__(128) gemm_uhat_kernel(const float* __restrict__ x,
                                                        const float* __restrict__ W) {
    extern __shared__ char raw[];
    __nv_bfloat16* Xh = (__nv_bfloat16*)raw;                 // [32][XPAD]
    __nv_bfloat16* Xl = Xh + 32 * XPAD;
    float* Wring = (float*)(Xl + 32 * XPAD);                 // [5][KSTAGE][WSTRIDE]

    const int s   = blockIdx.x;
    const int c   = blockIdx.y;
    const int tid = threadIdx.x;

    const float* Wp = W + ((size_t)c * SS + s) * (size_t)(DIN * DOUT);

    uint32_t wring_u32;
    {
        uint32_t tmp;
        asm("{ .reg .u64 t; cvta.to.shared.u64 t, %1; cvt.u32.u64 %0, t; }"
            : "=r"(tmp) : "l"((void*)Wring));
        wring_u32 = tmp;
    }

    const int wrow = tid >> 4;          // 0..7 (rows wrow, wrow+8)
    const int wseg = tid & 15;          // 16B segment within 256B row
#define ISSUE_STAGE(slot, chunk)                                              \
    {                                                                         \
        const float* srcb = Wp + ((chunk) * KSTAGE) * DOUT + wseg * 4;        \
        uint32_t dstb = wring_u32 + (uint32_t)(slot) * (KSTAGE * WSTRIDE * 4) \
                        + wseg * 16;                                          \
        asm volatile("cp.async.cg.shared.global [%0], [%1], 16;" ::           \
                     "r"(dstb + wrow * (WSTRIDE * 4)),                        \
                     "l"(srcb + wrow * DOUT) : "memory");                     \
        asm volatile("cp.async.cg.shared.global [%0], [%1], 16;" ::           \
                     "r"(dstb + (wrow + 8) * (WSTRIDE * 4)),                  \
                     "l"(srcb + (wrow + 8) * DOUT) : "memory");               \
        asm volatile("cp.async.commit_group;" ::: "memory");                  \
    }

    // prologue: chunks 0..3 in flight (4 groups)
    ISSUE_STAGE(0, 0);
    ISSUE_STAGE(1, 1);
    ISSUE_STAGE(2, 2);
    ISSUE_STAGE(3, 3);

    // ---- stage X tile (32 x 256 fp32) as hi/lo bf16 (RN split) ----
    for (int i = tid; i < 2048; i += 128) {
        const int b = i >> 6;
        const int k = (i & 63) * 4;
        float4 f = ((const float4*)(x + ((size_t)b * SS + s) * DIN))[i & 63];
        float hx = __bfloat162float(__float2bfloat16(f.x));
        float hy = __bfloat162float(__float2bfloat16(f.y));
        float hz = __bfloat162float(__float2bfloat16(f.z));
        float hw = __bfloat162float(__float2bfloat16(f.w));
        *(uint32_t*)(Xh + b * XPAD + k)     = pack_bf2(f.x, f.y);
        *(uint32_t*)(Xh + b * XPAD + k + 2) = pack_bf2(f.z, f.w);
        *(uint32_t*)(Xl + b * XPAD + k)     = pack_bf2(f.x - hx, f.y - hy);
        *(uint32_t*)(Xl + b * XPAD + k + 2) = pack_bf2(f.z - hz, f.w - hw);
    }

    const int lane = tid & 31;
    const int warp = tid >> 5;
    const int nb   = warp * 16;
    const int ar   = lane >> 2;          // 0..7
    const int kq   = (lane & 3) * 2;     // 0,2,4,6

    const int arow = lane & 15;
    const int akof = (lane >> 4) * 8;
    uint32_t xh_u32, xl_u32;
    {
        uint32_t t0, t1;
        asm("{ .reg .u64 t; cvta.to.shared.u64 t, %1; cvt.u32.u64 %0, t; }"
            : "=r"(t0) : "l"((void*)Xh));
        asm("{ .reg .u64 t; cvta.to.shared.u64 t, %1; cvt.u32.u64 %0, t; }"
            : "=r"(t1) : "l"((void*)Xl));
        xh_u32 = t0; xl_u32 = t1;
    }
    const uint32_t aoff0 = (uint32_t)((arow * XPAD + akof) * 2);
    const uint32_t aoff1 = (uint32_t)(((arow + 16) * XPAD + akof) * 2);

    float acc[2][2][4];
#pragma unroll
    for (int mt = 0; mt < 2; mt++)
#pragma unroll
        for (int nt = 0; nt < 2; nt++)
#pragma unroll
            for (int r = 0; r < 4; r++) acc[mt][nt][r] = 0.f;

    int slot_c = 0;   // consume slot
    int slot_p = 4;   // produce slot
#pragma unroll 4
    for (int ch = 0; ch < NCHUNK; ch++) {
        // committed groups so far = 4 + ch; wait 3 pending => chunks 0..ch landed
        asm volatile("cp.async.wait_group 3;" ::: "memory");
        __syncthreads();   // RAW (all threads' copies visible) + WAR (slot reuse)

        if (ch + 4 < NCHUNK) {
            ISSUE_STAGE(slot_p, ch + 4);
        } else {
            asm volatile("cp.async.commit_group;" ::: "memory");
        }
        if (++slot_p == NSTAGES) slot_p = 0;

        const float* Wst = Wring + slot_c * (KSTAGE * WSTRIDE);
        if (++slot_c == NSTAGES) slot_c = 0;

        const int k0 = ch * KSTAGE;   // global k for X

        uint32_t ah[2][4], al[2][4];
        LDSM_X4(ah[0][0], ah[0][1], ah[0][2], ah[0][3], xh_u32 + aoff0 + k0 * 2);
        LDSM_X4(ah[1][0], ah[1][1], ah[1][2], ah[1][3], xh_u32 + aoff1 + k0 * 2);
        LDSM_X4(al[0][0], al[0][1], al[0][2], al[0][3], xl_u32 + aoff0 + k0 * 2);
        LDSM_X4(al[1][0], al[1][1], al[1][2], al[1][3], xl_u32 + aoff1 + k0 * 2);

        uint32_t bh[2][2], bl[2][2];
#pragma unroll
        for (int nt = 0; nt < 2; nt++) {
            const int n = nb + nt * 8 + ar;
#pragma unroll
            for (int kg = 0; kg < 2; kg++) {
                const int krow = kq + kg * 8;
                float w0 = Wst[krow * WSTRIDE + n];
                float w1 = Wst[(krow + 1) * WSTRIDE + n];
                uint32_t u0 = __float_as_uint(w0);
                uint32_t u1 = __float_as_uint(w1);
                uint32_t hp;
                asm("prmt.b32 %0, %1, %2, 0x7632;" : "=r"(hp) : "r"(u0), "r"(u1));
                float l0 = w0 - __uint_as_float(u0 & 0xffff0000u);
                float l1 = w1 - __uint_as_float(u1 & 0xffff0000u);
                bh[nt][kg] = hp;
                bl[nt][kg] = pack_bf2(l0, l1);
            }
        }

#pragma unroll
        for (int mt = 0; mt < 2; mt++)
#pragma unroll
            for (int nt = 0; nt < 2; nt++) {
                MMA_BF16(acc[mt][nt], ah[mt], bh[nt]);
                MMA_BF16(acc[mt][nt], ah[mt], bl[nt]);
                MMA_BF16(acc[mt][nt], al[mt], bh[nt]);
            }
    }

    // ---- store: u_hat[b][s][c][o] ----
#pragma unroll
    for (int mt = 0; mt < 2; mt++) {
        const int row = ar + mt * 16;
#pragma unroll
        for (int nt = 0; nt < 2; nt++) {
            const int o = nb + nt * 8 + kq;
            float* p0 = g_uhat + (((size_t)row * SS + s) * CC + c) * DOUT + o;
            float* p1 = g_uhat + (((size_t)(row + 8) * SS + s) * CC + c) * DOUT + o;
            *(float2*)p0 = make_float2(acc[mt][nt][0], acc[mt][nt][1]);
            *(float2*)p1 = make_float2(acc[mt][nt][2], acc[mt][nt][3]);
        }
    }
}

// ---------------------------------------------------------------------------
// R1 (it0): s_j = (1/16) * sum_s u_hat[b,s,c,:] -> squash -> g_v.
// ---------------------------------------------------------------------------
__global__ void __launch_bounds__(256) r1_sj_kernel(void) {
    __shared__ float4 red4[256];
    __shared__ float sj[64];
    __shared__ float scl;

    const int bc  = blockIdx.x;
    const int b   = bc >> 4;
    const int c   = bc & 15;
    const int tid = threadIdx.x;

    const int col = tid & 15;
    const int sg  = tid >> 4;
    const float4* __restrict__ up4 = (const float4*)g_uhat;
    const size_t base = (size_t)b * SS * 256 + (size_t)c * 16;

    float4 acc = make_float4(0.f, 0.f, 0.f, 0.f);
#pragma unroll 8
    for (int s = sg; s < SS; s += 16) {
        float4 u = up4[base + (size_t)s * 256 + col];
        acc.x += u.x; acc.y += u.y; acc.z += u.z; acc.w += u.w;
    }
    acc.x *= (1.f/16.f); acc.y *= (1.f/16.f); acc.z *= (1.f/16.f); acc.w *= (1.f/16.f);
    red4[tid] = acc;
    __syncthreads();

    if (tid < 64) {
        const int cl = tid >> 2;
        const int cp = tid & 3;
        float t = 0.f;
#pragma unroll
        for (int g = 0; g < 16; g++) {
            float4 v = red4[g * 16 + cl];
            t += (cp == 0) ? v.x : (cp == 1) ? v.y : (cp == 2) ? v.z : v.w;
        }
        sj[tid] = t;
    }
    __syncthreads();

    if (tid < 32) {
        float t = sj[tid] * sj[tid] + sj[tid + 32] * sj[tid + 32];
#pragma unroll
        for (int off = 16; off; off >>= 1) t += __shfl_xor_sync(0xffffffffu, t, off);
        if (tid == 0) scl = sqrtf(t) / (1.0f + t);
    }
    __syncthreads();
    if (tid < 64)
        g_v[(size_t)bc * DOUT + tid] = sj[tid] * scl;
}

// ---------------------------------------------------------------------------
// F: fused (v-build) + agreement + b_ij + softmax + weighted partial s_j.
// 256 threads (8 warps), warp per s, 8 s per warp, 8 windows of 64 s.
// Partial s_j accumulated in warp-private SMEM (not registers) -> ~60 regs
// -> 4 blocks/SM instead of 2.
// mode 0: v from g_v, b_ij = dot, slices -> buf0
// mode 1: v from reduce(buf0)+squash, b_ij += dot, slices -> buf1
// ---------------------------------------------------------------------------
__global__ void __launch_bounds__(256) fused_route_kernel(int mode) {
    __shared__ float4 vs4[256];       // v[b] as (c,o)/4
    __shared__ float4 part4[8 * 256]; // per-warp partial s_j accumulators
    __shared__ float  sdot[8 * 16];   // per-warp dots / c_ij

    const int b    = blockIdx.x >> 3;
    const int w8   = blockIdx.x & 7;
    const int tid  = threadIdx.x;
    const int warp = tid >> 5;
    const int lane = tid & 31;
    const int hf   = lane >> 4;       // capsule parity
    const int l16  = lane & 15;

    // ---- build v in smem ----
    if (mode == 0) {
        vs4[tid] = ((const float4*)(g_v + (size_t)b * CC * DOUT))[tid];
    } else {
        float4 a = make_float4(0.f, 0.f, 0.f, 0.f);
#pragma unroll
        for (int w = 0; w < 8; w++) {
            float4 t = g_sjp[0][((size_t)w * BB + b) * 256 + tid];
            a.x += t.x; a.y += t.y; a.z += t.z; a.w += t.w;
        }
        float ss = a.x * a.x + a.y * a.y + a.z * a.z + a.w * a.w;
#pragma unroll
        for (int off = 8; off; off >>= 1) ss += __shfl_xor_sync(0xffffffffu, ss, off);
        float sc = sqrtf(ss) / (1.0f + ss);   // same across the 16-lane c-group
        vs4[tid] = make_float4(a.x * sc, a.y * sc, a.z * sc, a.w * sc);
    }

    // zero this warp's partial-s_j accumulator region
#pragma unroll
    for (int j = 0; j < 8; j++)
        part4[warp * 256 + j * 32 + lane] = make_float4(0.f, 0.f, 0.f, 0.f);
    __syncthreads();

    const int sbase = w8 * 64 + warp * 8;
    for (int si = 0; si < 8; si++) {
        const int s = sbase + si;
        const float4* __restrict__ up = (const float4*)(g_uhat + ((size_t)b * SS + s) * 1024);

        float4 u[8];
#pragma unroll
        for (int j = 0; j < 8; j++) u[j] = up[j * 32 + lane];

        // dots: d_c = sum_o u*v for c = 2j+hf; half-warp reduce per j
#pragma unroll
        for (int j = 0; j < 8; j++) {
            float4 v = vs4[(2 * j + hf) * 16 + l16];
            float d = u[j].x * v.x + u[j].y * v.y + u[j].z * v.z + u[j].w * v.w;
#pragma unroll
            for (int off = 8; off; off >>= 1) d += __shfl_xor_sync(0xffffffffu, d, off);
            if (l16 == 0) sdot[warp * 16 + 2 * j + hf] = d;
        }
        __syncwarp();

        // b_ij update + softmax (lanes 0..15)
        if (lane < 16) {
            float t = sdot[warp * 16 + lane];
            float* bp = g_b + ((size_t)b * SS + s) * CC;
            if (mode == 1) t += bp[lane];
            bp[lane] = t;
            float m = t;
#pragma unroll
            for (int off = 8; off; off >>= 1)
                m = fmaxf(m, __shfl_xor_sync(0xffffu, m, off));
            float e = __expf(t - m);
            float sum = e;
#pragma unroll
            for (int off = 8; off; off >>= 1)
                sum += __shfl_xor_sync(0xffffu, sum, off);
            sdot[warp * 16 + lane] = e / sum;      // c_ij
        }
        __syncwarp();

        // weighted accumulation into warp-private smem (reuses u regs)
#pragma unroll
        for (int j = 0; j < 8; j++) {
            float w = sdot[warp * 16 + 2 * j + hf];   // broadcast within half
            float4 q = part4[warp * 256 + j * 32 + lane];
            q.x += w * u[j].x; q.y += w * u[j].y;
            q.z += w * u[j].z; q.w += w * u[j].w;
            part4[warp * 256 + j * 32 + lane] = q;
        }
        __syncwarp();
    }
    __syncthreads();

    // block reduce 8 warps -> deterministic slice write
    float4 t = make_float4(0.f, 0.f, 0.f, 0.f);
#pragma unroll
    for (int w = 0; w < 8; w++) {
        float4 q = part4[w * 256 + tid];
        t.x += q.x; t.y += q.y; t.z += q.z; t.w += q.w;
    }
    g_sjp[mode][((size_t)w8 * BB + b) * 256 + tid] = t;
}

// ---------------------------------------------------------------------------
// finish: reduce buf1 slices -> s_j; squash -> d_out. grid B*C x 64.
// ---------------------------------------------------------------------------
__global__ void __launch_bounds__(64) finish_kernel(float* __restrict__ d_out) {
    __shared__ float sh[64];
    __shared__ float scl;
    const int bc = blockIdx.x;
    const int b  = bc >> 4;
    const int c  = bc & 15;
    const int o  = threadIdx.x;

    const float* base = (const float*)&g_sjp[1][0];
    float sjv = 0.f;
#pragma unroll
    for (int w = 0; w < 8; w++)
        sjv += base[((size_t)w * BB + b) * 1024 + c * 64 + o];

    sh[o] = sjv * sjv;
    __syncthreads();
    if (o < 32) {
        float t = sh[o] + sh[o + 32];
#pragma unroll
        for (int off = 16; off; off >>= 1) t += __shfl_xor_sync(0xffffffffu, t, off);
        if (o == 0) scl = sqrtf(t) / (1.0f + t);
    }
    __syncthreads();
    d_out[(size_t)bc * DOUT + o] = sjv * scl;
}

// ---------------------------------------------------------------------------
extern "C" void kernel_launch(void* const* d_in, const int* in_sizes, int n_in,
                              void* d_out, int out_size) {
    const float* x = (const float*)d_in[0];   // [B,S,din]
    const float* W = (const float*)d_in[1];   // [C,S,din,dout]
    float* out = (float*)d_out;               // [B,C,dout]

    const int gsm = 2 * 32 * XPAD * (int)sizeof(__nv_bfloat16)
                  + NSTAGES * KSTAGE * WSTRIDE * (int)sizeof(float); // 55552
    cudaFuncSetAttribute(gemm_uhat_kernel,
                         cudaFuncAttributeMaxDynamicSharedMemorySize, gsm);

    dim3 ggrid(SS, CC);
    gemm_uhat_kernel<<<ggrid, 128, gsm>>>(x, W);

    r1_sj_kernel<<<BB * CC, 256>>>();         // it0: uniform -> v0
    fused_route_kernel<<<BB * 8, 256>>>(0);   // dots(v0); b=dot; softmax; s_j -> buf0
    fused_route_kernel<<<BB * 8, 256>>>(1);   // v1=squash(buf0); b+=dot; s_j -> buf1
    finish_kernel<<<BB * CC, 64>>>(out);      // v2=squash(buf1) -> out
}

// round 12
// speedup vs baseline: 1.0004x; 1.0004x over previous
#include <cuda_runtime.h>
#include <cuda_bf16.h>
#include <math.h>
#include <stdint.h>

#define BB   32
#define SS   512
#define CC   16
#define DIN  256
#define DOUT 64

#define XPAD 264       // bf16 row stride for Xs[b][k] (528B rows, ldmatrix conflict-free)
#define WSTRIDE 68     // fp32 row stride for W stage rows (bank = 8q+ar, conflict-free)
#define KSTAGE 16      // K rows per cp.async stage
#define NSTAGES 5
#define NCHUNK 16      // 256 / 16

// Scratch (allocation-free rule: __device__ globals)
__device__ float g_uhat[(size_t)BB * SS * CC * DOUT]; // 64 MiB, [b][s][c][o]
__device__ float g_b[(size_t)BB * SS * CC];           // b_ij [b][s][c]
__device__ float g_v[(size_t)BB * CC * DOUT];         // v_j  [b][c][o] (it0 only)
__device__ float4 g_sjp[2][(size_t)8 * BB * 256];     // s_j slices [buf][w8][b][(c,o)/4]

__device__ __forceinline__ uint32_t pack_bf2(float a, float b) {
    __nv_bfloat162 t = __floats2bfloat162_rn(a, b);
    return *reinterpret_cast<uint32_t*>(&t);
}

#define MMA_BF16(d, a, b)                                                     \
    asm volatile(                                                             \
        "mma.sync.aligned.m16n8k16.row.col.f32.bf16.bf16.f32 "                \
        "{%0,%1,%2,%3},{%4,%5,%6,%7},{%8,%9},{%0,%1,%2,%3};"                  \
        : "+f"(d[0]), "+f"(d[1]), "+f"(d[2]), "+f"(d[3])                      \
        : "r"(a[0]), "r"(a[1]), "r"(a[2]), "r"(a[3]), "r"(b[0]), "r"(b[1]))

#define LDSM_X4(r0, r1, r2, r3, addr)                                         \
    asm volatile("ldmatrix.sync.aligned.m8n8.x4.shared.b16 {%0,%1,%2,%3}, [%4];" \
                 : "=r"(r0), "=r"(r1), "=r"(r2), "=r"(r3) : "r"(addr))

// ---------------------------------------------------------------------------
// GEMM: u_hat[b,s,c,o] = sum_i x[b,s,i] * W[c,s,i,o]
// grid (S, C), 128 threads, occ 4. W streamed raw fp32 via 5-stage x 16-row
// cp.async ring, ONE barrier per chunk; split-bf16 (truncation) conversion
// fused into B-fragment build; A via ldmatrix from pre-split hi/lo X tile.
// ---------------------------------------------------------------------------
__global__ void __launch_bounds__(128) gemm_uhat_kernel(const float* __restrict__ x,
                                                        const float* __restrict__ W) {
    extern __shared__ char raw[];
    __nv_bfloat16* Xh = (__nv_bfloat16*)raw;                 // [32][XPAD]
    __nv_bfloat16* Xl = Xh + 32 * XPAD;
    float* Wring = (float*)(Xl + 32 * XPAD);                 // [5][KSTAGE][WSTRIDE]

    const int s   = blockIdx.x;
    const int c   = blockIdx.y;
    const int tid = threadIdx.x;

    const float* Wp = W + ((size_t)c * SS + s) * (size_t)(DIN * DOUT);

    uint32_t wring_u32;
    {
        uint32_t tmp;
        asm("{ .reg .u64 t; cvta.to.shared.u64 t, %1; cvt.u32.u64 %0, t; }"
            : "=r"(tmp) : "l"((void*)Wring));
        wring_u32 = tmp;
    }

    const int wrow = tid >> 4;          // 0..7 (rows wrow, wrow+8)
    const int wseg = tid & 15;          // 16B segment within 256B row
#define ISSUE_STAGE(slot, chunk)                                              \
    {                                                                         \
        const float* srcb = Wp + ((chunk) * KSTAGE) * DOUT + wseg * 4;        \
        uint32_t dstb = wring_u32 + (uint32_t)(slot) * (KSTAGE * WSTRIDE * 4) \
                        + wseg * 16;                                          \
        asm volatile("cp.async.cg.shared.global [%0], [%1], 16;" ::           \
                     "r"(dstb + wrow * (WSTRIDE * 4)),                        \
                     "l"(srcb + wrow * DOUT) : "memory");                     \
        asm volatile("cp.async.cg.shared.global [%0], [%1], 16;" ::           \
                     "r"(dstb + (wrow + 8) * (WSTRIDE * 4)),                  \
                     "l"(srcb + (wrow + 8) * DOUT) : "memory");               \
        asm volatile("cp.async.commit_group;" ::: "memory");                  \
    }

    // prologue: chunks 0..3 in flight (4 groups)
    ISSUE_STAGE(0, 0);
    ISSUE_STAGE(1, 1);
    ISSUE_STAGE(2, 2);
    ISSUE_STAGE(3, 3);

    // ---- stage X tile (32 x 256 fp32) as hi/lo bf16 (RN split) ----
    for (int i = tid; i < 2048; i += 128) {
        const int b = i >> 6;
        const int k = (i & 63) * 4;
        float4 f = ((const float4*)(x + ((size_t)b * SS + s) * DIN))[i & 63];
        float hx = __bfloat162float(__float2bfloat16(f.x));
        float hy = __bfloat162float(__float2bfloat16(f.y));
        float hz = __bfloat162float(__float2bfloat16(f.z));
        float hw = __bfloat162float(__float2bfloat16(f.w));
        *(uint32_t*)(Xh + b * XPAD + k)     = pack_bf2(f.x, f.y);
        *(uint32_t*)(Xh + b * XPAD + k + 2) = pack_bf2(f.z, f.w);
        *(uint32_t*)(Xl + b * XPAD + k)     = pack_bf2(f.x - hx, f.y - hy);
        *(uint32_t*)(Xl + b * XPAD + k + 2) = pack_bf2(f.z - hz, f.w - hw);
    }

    const int lane = tid & 31;
    const int warp = tid >> 5;
    const int nb   = warp * 16;
    const int ar   = lane >> 2;          // 0..7
    const int kq   = (lane & 3) * 2;     // 0,2,4,6

    const int arow = lane & 15;
    const int akof = (lane >> 4) * 8;
    uint32_t xh_u32, xl_u32;
    {
        uint32_t t0, t1;
        asm("{ .reg .u64 t; cvta.to.shared.u64 t, %1; cvt.u32.u64 %0, t; }"
            : "=r"(t0) : "l"((void*)Xh));
        asm("{ .reg .u64 t; cvta.to.shared.u64 t, %1; cvt.u32.u64 %0, t; }"
            : "=r"(t1) : "l"((void*)Xl));
        xh_u32 = t0; xl_u32 = t1;
    }
    const uint32_t aoff0 = (uint32_t)((arow * XPAD + akof) * 2);
    const uint32_t aoff1 = (uint32_t)(((arow + 16) * XPAD + akof) * 2);

    float acc[2][2][4];
#pragma unroll
    for (int mt = 0; mt < 2; mt++)
#pragma unroll
        for (int nt = 0; nt < 2; nt++)
#pragma unroll
            for (int r = 0; r < 4; r++) acc[mt][nt][r] = 0.f;

    int slot_c = 0;   // consume slot
    int slot_p = 4;   // produce slot
#pragma unroll 4
    for (int ch = 0; ch < NCHUNK; ch++) {
        // committed groups so far = 4 + ch; wait 3 pending => chunks 0..ch landed
        asm volatile("cp.async.wait_group 3;" ::: "memory");
        __syncthreads();   // RAW (all threads' copies visible) + WAR (slot reuse)

        if (ch + 4 < NCHUNK) {
            ISSUE_STAGE(slot_p, ch + 4);
        } else {
            asm volatile("cp.async.commit_group;" ::: "memory");
        }
        if (++slot_p == NSTAGES) slot_p = 0;

        const float* Wst = Wring + slot_c * (KSTAGE * WSTRIDE);
        if (++slot_c == NSTAGES) slot_c = 0;

        const int k0 = ch * KSTAGE;   // global k for X

        uint32_t ah[2][4], al[2][4];
        LDSM_X4(ah[0][0], ah[0][1], ah[0][2], ah[0][3], xh_u32 + aoff0 + k0 * 2);
        LDSM_X4(ah[1][0], ah[1][1], ah[1][2], ah[1][3], xh_u32 + aoff1 + k0 * 2);
        LDSM_X4(al[0][0], al[0][1], al[0][2], al[0][3], xl_u32 + aoff0 + k0 * 2);
        LDSM_X4(al[1][0], al[1][1], al[1][2], al[1][3], xl_u32 + aoff1 + k0 * 2);

        uint32_t bh[2][2], bl[2][2];
#pragma unroll
        for (int nt = 0; nt < 2; nt++) {
            const int n = nb + nt * 8 + ar;
#pragma unroll
            for (int kg = 0; kg < 2; kg++) {
                const int krow = kq + kg * 8;
                float w0 = Wst[krow * WSTRIDE + n];
                float w1 = Wst[(krow + 1) * WSTRIDE + n];
                uint32_t u0 = __float_as_uint(w0);
                uint32_t u1 = __float_as_uint(w1);
                uint32_t hp;
                asm("prmt.b32 %0, %1, %2, 0x7632;" : "=r"(hp) : "r"(u0), "r"(u1));
                float l0 = w0 - __uint_as_float(u0 & 0xffff0000u);
                float l1 = w1 - __uint_as_float(u1 & 0xffff0000u);
                bh[nt][kg] = hp;
                bl[nt][kg] = pack_bf2(l0, l1);
            }
        }

#pragma unroll
        for (int mt = 0; mt < 2; mt++)
#pragma unroll
            for (int nt = 0; nt < 2; nt++) {
                MMA_BF16(acc[mt][nt], ah[mt], bh[nt]);
                MMA_BF16(acc[mt][nt], ah[mt], bl[nt]);
                MMA_BF16(acc[mt][nt], al[mt], bh[nt]);
            }
    }

    // ---- store: u_hat[b][s][c][o] ----
#pragma unroll
    for (int mt = 0; mt < 2; mt++) {
        const int row = ar + mt * 16;
#pragma unroll
        for (int nt = 0; nt < 2; nt++) {
            const int o = nb + nt * 8 + kq;
            float* p0 = g_uhat + (((size_t)row * SS + s) * CC + c) * DOUT + o;
            float* p1 = g_uhat + (((size_t)(row + 8) * SS + s) * CC + c) * DOUT + o;
            *(float2*)p0 = make_float2(acc[mt][nt][0], acc[mt][nt][1]);
            *(float2*)p1 = make_float2(acc[mt][nt][2], acc[mt][nt][3]);
        }
    }
}

// ---------------------------------------------------------------------------
// R1 (it0): s_j = (1/16) * sum_s u_hat[b,s,c,:] -> squash -> g_v.
// ---------------------------------------------------------------------------
__global__ void __launch_bounds__(256) r1_sj_kernel(void) {
    __shared__ float4 red4[256];
    __shared__ float sj[64];
    __shared__ float scl;

    const int bc  = blockIdx.x;
    const int b   = bc >> 4;
    const int c   = bc & 15;
    const int tid = threadIdx.x;

    const int col = tid & 15;
    const int sg  = tid >> 4;
    const float4* __restrict__ up4 = (const float4*)g_uhat;
    const size_t base = (size_t)b * SS * 256 + (size_t)c * 16;

    float4 acc = make_float4(0.f, 0.f, 0.f, 0.f);
#pragma unroll 8
    for (int s = sg; s < SS; s += 16) {
        float4 u = up4[base + (size_t)s * 256 + col];
        acc.x += u.x; acc.y += u.y; acc.z += u.z; acc.w += u.w;
    }
    acc.x *= (1.f/16.f); acc.y *= (1.f/16.f); acc.z *= (1.f/16.f); acc.w *= (1.f/16.f);
    red4[tid] = acc;
    __syncthreads();

    if (tid < 64) {
        const int cl = tid >> 2;
        const int cp = tid & 3;
        float t = 0.f;
#pragma unroll
        for (int g = 0; g < 16; g++) {
            float4 v = red4[g * 16 + cl];
            t += (cp == 0) ? v.x : (cp == 1) ? v.y : (cp == 2) ? v.z : v.w;
        }
        sj[tid] = t;
    }
    __syncthreads();

    if (tid < 32) {
        float t = sj[tid] * sj[tid] + sj[tid + 32] * sj[tid + 32];
#pragma unroll
        for (int off = 16; off; off >>= 1) t += __shfl_xor_sync(0xffffffffu, t, off);
        if (tid == 0) scl = sqrtf(t) / (1.0f + t);
    }
    __syncthreads();
    if (tid < 64)
        g_v[(size_t)bc * DOUT + tid] = sj[tid] * scl;
}

// ---------------------------------------------------------------------------
// F: fused (v-build) + agreement + b_ij + softmax + weighted partial s_j.
// 256 threads (8 warps), warp per s, 8 s per warp, 8 windows of 64 s.
// Partial s_j accumulated in warp-private SMEM; low regs (~56) so the
// occupancy limit is smem -> full shared carveout requested host-side
// to reach 4 blocks/SM.
// mode 0: v from g_v, b_ij = dot, slices -> buf0
// mode 1: v from reduce(buf0)+squash, b_ij += dot, slices -> buf1
// ---------------------------------------------------------------------------
__global__ void __launch_bounds__(256) fused_route_kernel(int mode) {
    __shared__ float4 vs4[256];       // v[b] as (c,o)/4
    __shared__ float4 part4[8 * 256]; // per-warp partial s_j accumulators
    __shared__ float  sdot[8 * 16];   // per-warp dots / c_ij

    const int b    = blockIdx.x >> 3;
    const int w8   = blockIdx.x & 7;
    const int tid  = threadIdx.x;
    const int warp = tid >> 5;
    const int lane = tid & 31;
    const int hf   = lane >> 4;       // capsule parity
    const int l16  = lane & 15;

    // ---- build v in smem ----
    if (mode == 0) {
        vs4[tid] = ((const float4*)(g_v + (size_t)b * CC * DOUT))[tid];
    } else {
        float4 a = make_float4(0.f, 0.f, 0.f, 0.f);
#pragma unroll
        for (int w = 0; w < 8; w++) {
            float4 t = g_sjp[0][((size_t)w * BB + b) * 256 + tid];
            a.x += t.x; a.y += t.y; a.z += t.z; a.w += t.w;
        }
        float ss = a.x * a.x + a.y * a.y + a.z * a.z + a.w * a.w;
#pragma unroll
        for (int off = 8; off; off >>= 1) ss += __shfl_xor_sync(0xffffffffu, ss, off);
        float sc = sqrtf(ss) / (1.0f + ss);   // same across the 16-lane c-group
        vs4[tid] = make_float4(a.x * sc, a.y * sc, a.z * sc, a.w * sc);
    }

    // zero this warp's partial-s_j accumulator region
#pragma unroll
    for (int j = 0; j < 8; j++)
        part4[warp * 256 + j * 32 + lane] = make_float4(0.f, 0.f, 0.f, 0.f);
    __syncthreads();

    const int sbase = w8 * 64 + warp * 8;
    for (int si = 0; si < 8; si++) {
        const int s = sbase + si;
        const float4* __restrict__ up = (const float4*)(g_uhat + ((size_t)b * SS + s) * 1024);

        float4 u[8];
#pragma unroll
        for (int j = 0; j < 8; j++) u[j] = up[j * 32 + lane];

        // dots: d_c = sum_o u*v for c = 2j+hf; half-warp reduce per j
#pragma unroll
        for (int j = 0; j < 8; j++) {
            float4 v = vs4[(2 * j + hf) * 16 + l16];
            float d = u[j].x * v.x + u[j].y * v.y + u[j].z * v.z + u[j].w * v.w;
#pragma unroll
            for (int off = 8; off; off >>= 1) d += __shfl_xor_sync(0xffffffffu, d, off);
            if (l16 == 0) sdot[warp * 16 + 2 * j + hf] = d;
        }
        __syncwarp();

        // b_ij update + softmax (lanes 0..15)
        if (lane < 16) {
            float t = sdot[warp * 16 + lane];
            float* bp = g_b + ((size_t)b * SS + s) * CC;
            if (mode == 1) t += bp[lane];
            bp[lane] = t;
            float m = t;
#pragma unroll
            for (int off = 8; off; off >>= 1)
                m = fmaxf(m, __shfl_xor_sync(0xffffu, m, off));
            float e = __expf(t - m);
            float sum = e;
#pragma unroll
            for (int off = 8; off; off >>= 1)
                sum += __shfl_xor_sync(0xffffu, sum, off);
            sdot[warp * 16 + lane] = e / sum;      // c_ij
        }
        __syncwarp();

        // weighted accumulation into warp-private smem (reuses u regs)
#pragma unroll
        for (int j = 0; j < 8; j++) {
            float w = sdot[warp * 16 + 2 * j + hf];   // broadcast within half
            float4 q = part4[warp * 256 + j * 32 + lane];
            q.x += w * u[j].x; q.y += w * u[j].y;
            q.z += w * u[j].z; q.w += w * u[j].w;
            part4[warp * 256 + j * 32 + lane] = q;
        }
        __syncwarp();
    }
    __syncthreads();

    // block reduce 8 warps -> deterministic slice write
    float4 t = make_float4(0.f, 0.f, 0.f, 0.f);
#pragma unroll
    for (int w = 0; w < 8; w++) {
        float4 q = part4[w * 256 + tid];
        t.x += q.x; t.y += q.y; t.z += q.z; t.w += q.w;
    }
    g_sjp[mode][((size_t)w8 * BB + b) * 256 + tid] = t;
}

// ---------------------------------------------------------------------------
// finish: reduce buf1 slices -> s_j; squash -> d_out. grid B*C x 64.
// ---------------------------------------------------------------------------
__global__ void __launch_bounds__(64) finish_kernel(float* __restrict__ d_out) {
    __shared__ float sh[64];
    __shared__ float scl;
    const int bc = blockIdx.x;
    const int b  = bc >> 4;
    const int c  = bc & 15;
    const int o  = threadIdx.x;

    const float* base = (const float*)&g_sjp[1][0];
    float sjv = 0.f;
#pragma unroll
    for (int w = 0; w < 8; w++)
        sjv += base[((size_t)w * BB + b) * 1024 + c * 64 + o];

    sh[o] = sjv * sjv;
    __syncthreads();
    if (o < 32) {
        float t = sh[o] + sh[o + 32];
#pragma unroll
        for (int off = 16; off; off >>= 1) t += __shfl_xor_sync(0xffffffffu, t, off);
        if (o == 0) scl = sqrtf(t) / (1.0f + t);
    }
    __syncthreads();
    d_out[(size_t)bc * DOUT + o] = sjv * scl;
}

// ---------------------------------------------------------------------------
extern "C" void kernel_launch(void* const* d_in, const int* in_sizes, int n_in,
                              void* d_out, int out_size) {
    const float* x = (const float*)d_in[0];   // [B,S,din]
    const float* W = (const float*)d_in[1];   // [C,S,din,dout]
    float* out = (float*)d_out;               // [B,C,dout]

    const int gsm = 2 * 32 * XPAD * (int)sizeof(__nv_bfloat16)
                  + NSTAGES * KSTAGE * WSTRIDE * (int)sizeof(float); // 55552
    cudaFuncSetAttribute(gemm_uhat_kernel,
                         cudaFuncAttributeMaxDynamicSharedMemorySize, gsm);
    // fused_route is smem-carveout-limited at default (~100KB -> 2 blocks/SM).
    // Request full shared carveout so 4 blocks (4 x 36.9KB = 148KB <= 228KB) fit.
    cudaFuncSetAttribute(fused_route_kernel,
                         cudaFuncAttributePreferredSharedMemoryCarveout, 100);

    dim3 ggrid(SS, CC);
    gemm_uhat_kernel<<<ggrid, 128, gsm>>>(x, W);

    r1_sj_kernel<<<BB * CC, 256>>>();         // it0: uniform -> v0
    fused_route_kernel<<<BB * 8, 256>>>(0);   // dots(v0); b=dot; softmax; s_j -> buf0
    fused_route_kernel<<<BB * 8, 256>>>(1);   // v1=squash(buf0); b+=dot; s_j -> buf1
    finish_kernel<<<BB * CC, 64>>>(out);      // v2=squash(buf1) -> out
}

// round 13
// speedup vs baseline: 1.1157x; 1.1153x over previous
#include <cuda_runtime.h>
#include <cuda_bf16.h>
#include <math.h>
#include <stdint.h>

#define BB   32
#define SS   512
#define CC   16
#define DIN  256
#define DOUT 64

#define XPAD 264       // bf16 row stride for Xs[b][k] (528B rows, ldmatrix conflict-free)
#define WSTRIDE 68     // fp32 row stride for W stage rows (bank = 8q+ar, conflict-free)
#define KSTAGE 16      // K rows per cp.async stage
#define NSTAGES 5
#define NCHUNK 16      // 256 / 16
#define RINGSZ (NSTAGES * KSTAGE * WSTRIDE)   // floats per capsule ring

// Scratch (allocation-free rule: __device__ globals)
__device__ float g_uhat[(size_t)BB * SS * CC * DOUT]; // 64 MiB, [b][s][c][o]
__device__ float g_b[(size_t)BB * SS * CC];           // b_ij [b][s][c]
__device__ float g_v[(size_t)BB * CC * DOUT];         // v_j  [b][c][o] (it0 only)
__device__ float4 g_sjp[2][(size_t)8 * BB * 256];     // s_j slices [buf][w8][b][(c,o)/4]

__device__ __forceinline__ uint32_t pack_bf2(float a, float b) {
    __nv_bfloat162 t = __floats2bfloat162_rn(a, b);
    return *reinterpret_cast<uint32_t*>(&t);
}

#define MMA_BF16(d, a, b)                                                     \
    asm volatile(                                                             \
        "mma.sync.aligned.m16n8k16.row.col.f32.bf16.bf16.f32 "                \
        "{%0,%1,%2,%3},{%4,%5,%6,%7},{%8,%9},{%0,%1,%2,%3};"                  \
        : "+f"(d[0]), "+f"(d[1]), "+f"(d[2]), "+f"(d[3])                      \
        : "r"(a[0]), "r"(a[1]), "r"(a[2]), "r"(a[3]), "r"(b[0]), "r"(b[1]))

#define LDSM_X4(r0, r1, r2, r3, addr)                                         \
    asm volatile("ldmatrix.sync.aligned.m8n8.x4.shared.b16 {%0,%1,%2,%3}, [%4];" \
                 : "=r"(r0), "=r"(r1), "=r"(r2), "=r"(r3) : "r"(addr))

// ---------------------------------------------------------------------------
// GEMM: u_hat[b,s,c,o] = sum_i x[b,s,i] * W[c,s,i,o]
// grid (S, C/2), 256 threads. TWO capsules (c, c+8) per block share one staged
// X tile; each 128-thread half streams its own W slab through a 5-stage
// cp.async ring (per-thread group accounting). Split-bf16 (truncation)
// conversion fused into B-fragment build; A via ldmatrix.
// ---------------------------------------------------------------------------
__global__ void __launch_bounds__(256) gemm_uhat_kernel(const float* __restrict__ x,
                                                        const float* __restrict__ W) {
    extern __shared__ char raw[];
    __nv_bfloat16* Xh = (__nv_bfloat16*)raw;                 // [32][XPAD]
    __nv_bfloat16* Xl = Xh + 32 * XPAD;
    float* Wring = (float*)(Xl + 32 * XPAD);                 // [2][NSTAGES][KSTAGE][WSTRIDE]

    const int s   = blockIdx.x;
    const int tid = threadIdx.x;
    const int cw  = tid >> 7;            // capsule half: 0 or 1
    const int wg  = tid & 127;           // tid within half
    const int cc  = blockIdx.y + cw * 8; // this half's capsule

    const float* Wp = W + ((size_t)cc * SS + s) * (size_t)(DIN * DOUT);
    float* myring = Wring + cw * RINGSZ;

    uint32_t ring_u32;
    {
        uint32_t tmp;
        asm("{ .reg .u64 t; cvta.to.shared.u64 t, %1; cvt.u32.u64 %0, t; }"
            : "=r"(tmp) : "l"((void*)myring));
        ring_u32 = tmp;
    }

    const int wrow = wg >> 4;           // 0..7 (rows wrow, wrow+8)
    const int wseg = wg & 15;           // 16B segment within 256B row
#define ISSUE_STAGE(slot, chunk)                                              \
    {                                                                         \
        const float* srcb = Wp + ((chunk) * KSTAGE) * DOUT + wseg * 4;        \
        uint32_t dstb = ring_u32 + (uint32_t)(slot) * (KSTAGE * WSTRIDE * 4)  \
                        + wseg * 16;                                          \
        asm volatile("cp.async.cg.shared.global [%0], [%1], 16;" ::           \
                     "r"(dstb + wrow * (WSTRIDE * 4)),                        \
                     "l"(srcb + wrow * DOUT) : "memory");                     \
        asm volatile("cp.async.cg.shared.global [%0], [%1], 16;" ::           \
                     "r"(dstb + (wrow + 8) * (WSTRIDE * 4)),                  \
                     "l"(srcb + (wrow + 8) * DOUT) : "memory");               \
        asm volatile("cp.async.commit_group;" ::: "memory");                  \
    }

    // prologue: chunks 0..3 in flight (4 groups per thread)
    ISSUE_STAGE(0, 0);
    ISSUE_STAGE(1, 1);
    ISSUE_STAGE(2, 2);
    ISSUE_STAGE(3, 3);

    // ---- stage X tile (32 x 256 fp32) as hi/lo bf16 (RN split), all 256 thr ----
    for (int i = tid; i < 2048; i += 256) {
        const int b = i >> 6;
        const int k = (i & 63) * 4;
        float4 f = ((const float4*)(x + ((size_t)b * SS + s) * DIN))[i & 63];
        float hx = __bfloat162float(__float2bfloat16(f.x));
        float hy = __bfloat162float(__float2bfloat16(f.y));
        float hz = __bfloat162float(__float2bfloat16(f.z));
        float hw = __bfloat162float(__float2bfloat16(f.w));
        *(uint32_t*)(Xh + b * XPAD + k)     = pack_bf2(f.x, f.y);
        *(uint32_t*)(Xh + b * XPAD + k + 2) = pack_bf2(f.z, f.w);
        *(uint32_t*)(Xl + b * XPAD + k)     = pack_bf2(f.x - hx, f.y - hy);
        *(uint32_t*)(Xl + b * XPAD + k + 2) = pack_bf2(f.z - hz, f.w - hw);
    }

    const int lane = tid & 31;
    const int w4   = (tid >> 5) & 3;     // warp within half
    const int nb   = w4 * 16;
    const int ar   = lane >> 2;          // 0..7
    const int kq   = (lane & 3) * 2;     // 0,2,4,6

    const int arow = lane & 15;
    const int akof = (lane >> 4) * 8;
    uint32_t xh_u32, xl_u32;
    {
        uint32_t t0, t1;
        asm("{ .reg .u64 t; cvta.to.shared.u64 t, %1; cvt.u32.u64 %0, t; }"
            : "=r"(t0) : "l"((void*)Xh));
        asm("{ .reg .u64 t; cvta.to.shared.u64 t, %1; cvt.u32.u64 %0, t; }"
            : "=r"(t1) : "l"((void*)Xl));
        xh_u32 = t0; xl_u32 = t1;
    }
    const uint32_t aoff0 = (uint32_t)((arow * XPAD + akof) * 2);
    const uint32_t aoff1 = (uint32_t)(((arow + 16) * XPAD + akof) * 2);

    float acc[2][2][4];
#pragma unroll
    for (int mt = 0; mt < 2; mt++)
#pragma unroll
        for (int nt = 0; nt < 2; nt++)
#pragma unroll
            for (int r = 0; r < 4; r++) acc[mt][nt][r] = 0.f;

    int slot_c = 0;   // consume slot
    int slot_p = 4;   // produce slot
#pragma unroll 4
    for (int ch = 0; ch < NCHUNK; ch++) {
        // per-thread committed groups = 4 + ch; <=3 pending => chunks 0..ch landed
        asm volatile("cp.async.wait_group 3;" ::: "memory");
        __syncthreads();   // RAW + WAR across both halves

        if (ch + 4 < NCHUNK) {
            ISSUE_STAGE(slot_p, ch + 4);
        } else {
            asm volatile("cp.async.commit_group;" ::: "memory");
        }
        if (++slot_p == NSTAGES) slot_p = 0;

        const float* Wst = myring + slot_c * (KSTAGE * WSTRIDE);
        if (++slot_c == NSTAGES) slot_c = 0;

        const int k0 = ch * KSTAGE;   // global k for X

        uint32_t ah[2][4], al[2][4];
        LDSM_X4(ah[0][0], ah[0][1], ah[0][2], ah[0][3], xh_u32 + aoff0 + k0 * 2);
        LDSM_X4(ah[1][0], ah[1][1], ah[1][2], ah[1][3], xh_u32 + aoff1 + k0 * 2);
        LDSM_X4(al[0][0], al[0][1], al[0][2], al[0][3], xl_u32 + aoff0 + k0 * 2);
        LDSM_X4(al[1][0], al[1][1], al[1][2], al[1][3], xl_u32 + aoff1 + k0 * 2);

        uint32_t bh[2][2], bl[2][2];
#pragma unroll
        for (int nt = 0; nt < 2; nt++) {
            const int n = nb + nt * 8 + ar;
#pragma unroll
            for (int kg = 0; kg < 2; kg++) {
                const int krow = kq + kg * 8;
                float w0 = Wst[krow * WSTRIDE + n];
                float w1 = Wst[(krow + 1) * WSTRIDE + n];
                uint32_t u0 = __float_as_uint(w0);
                uint32_t u1 = __float_as_uint(w1);
                uint32_t hp;
                asm("prmt.b32 %0, %1, %2, 0x7632;" : "=r"(hp) : "r"(u0), "r"(u1));
                float l0 = w0 - __uint_as_float(u0 & 0xffff0000u);
                float l1 = w1 - __uint_as_float(u1 & 0xffff0000u);
                bh[nt][kg] = hp;
                bl[nt][kg] = pack_bf2(l0, l1);
            }
        }

#pragma unroll
        for (int mt = 0; mt < 2; mt++)
#pragma unroll
            for (int nt = 0; nt < 2; nt++) {
                MMA_BF16(acc[mt][nt], ah[mt], bh[nt]);
                MMA_BF16(acc[mt][nt], ah[mt], bl[nt]);
                MMA_BF16(acc[mt][nt], al[mt], bh[nt]);
            }
    }

    // ---- store: u_hat[b][s][c][o] ----
#pragma unroll
    for (int mt = 0; mt < 2; mt++) {
        const int row = ar + mt * 16;
#pragma unroll
        for (int nt = 0; nt < 2; nt++) {
            const int o = nb + nt * 8 + kq;
            float* p0 = g_uhat + (((size_t)row * SS + s) * CC + cc) * DOUT + o;
            float* p1 = g_uhat + (((size_t)(row + 8) * SS + s) * CC + cc) * DOUT + o;
            *(float2*)p0 = make_float2(acc[mt][nt][0], acc[mt][nt][1]);
            *(float2*)p1 = make_float2(acc[mt][nt][2], acc[mt][nt][3]);
        }
    }
}

// ---------------------------------------------------------------------------
// R1 (it0): s_j = (1/16) * sum_s u_hat[b,s,c,:] -> squash -> g_v.
// ---------------------------------------------------------------------------
__global__ void __launch_bounds__(256) r1_sj_kernel(void) {
    __shared__ float4 red4[256];
    __shared__ float sj[64];
    __shared__ float scl;

    const int bc  = blockIdx.x;
    const int b   = bc >> 4;
    const int c   = bc & 15;
    const int tid = threadIdx.x;

    const int col = tid & 15;
    const int sg  = tid >> 4;
    const float4* __restrict__ up4 = (const float4*)g_uhat;
    const size_t base = (size_t)b * SS * 256 + (size_t)c * 16;

    float4 acc = make_float4(0.f, 0.f, 0.f, 0.f);
#pragma unroll 8
    for (int s = sg; s < SS; s += 16) {
        float4 u = up4[base + (size_t)s * 256 + col];
        acc.x += u.x; acc.y += u.y; acc.z += u.z; acc.w += u.w;
    }
    acc.x *= (1.f/16.f); acc.y *= (1.f/16.f); acc.z *= (1.f/16.f); acc.w *= (1.f/16.f);
    red4[tid] = acc;
    __syncthreads();

    if (tid < 64) {
        const int cl = tid >> 2;
        const int cp = tid & 3;
        float t = 0.f;
#pragma unroll
        for (int g = 0; g < 16; g++) {
            float4 v = red4[g * 16 + cl];
            t += (cp == 0) ? v.x : (cp == 1) ? v.y : (cp == 2) ? v.z : v.w;
        }
        sj[tid] = t;
    }
    __syncthreads();

    if (tid < 32) {
        float t = sj[tid] * sj[tid] + sj[tid + 32] * sj[tid + 32];
#pragma unroll
        for (int off = 16; off; off >>= 1) t += __shfl_xor_sync(0xffffffffu, t, off);
        if (tid == 0) scl = sqrtf(t) / (1.0f + t);
    }
    __syncthreads();
    if (tid < 64)
        g_v[(size_t)bc * DOUT + tid] = sj[tid] * scl;
}

// ---------------------------------------------------------------------------
// F: fused (v-build) + agreement + b_ij + softmax + weighted partial s_j.
// 256 threads (8 warps), warp per s, 8 s per warp, 8 windows of 64 s.
// R10 config: register accumulators (89 regs, best measured).
// mode 0: v from g_v, b_ij = dot, slices -> buf0
// mode 1: v from reduce(buf0)+squash, b_ij += dot, slices -> buf1
// ---------------------------------------------------------------------------
__global__ void __launch_bounds__(256) fused_route_kernel(int mode) {
    __shared__ float4 vs4[256];       // v[b] as (c,o)/4
    __shared__ float4 part4[8 * 256]; // per-warp partial s_j
    __shared__ float  sdot[8 * 16];   // per-warp dots / c_ij

    const int b    = blockIdx.x >> 3;
    const int w8   = blockIdx.x & 7;
    const int tid  = threadIdx.x;
    const int warp = tid >> 5;
    const int lane = tid & 31;
    const int hf   = lane >> 4;       // capsule parity
    const int l16  = lane & 15;

    // ---- build v in smem ----
    if (mode == 0) {
        vs4[tid] = ((const float4*)(g_v + (size_t)b * CC * DOUT))[tid];
    } else {
        float4 a = make_float4(0.f, 0.f, 0.f, 0.f);
#pragma unroll
        for (int w = 0; w < 8; w++) {
            float4 t = g_sjp[0][((size_t)w * BB + b) * 256 + tid];
            a.x += t.x; a.y += t.y; a.z += t.z; a.w += t.w;
        }
        float ss = a.x * a.x + a.y * a.y + a.z * a.z + a.w * a.w;
#pragma unroll
        for (int off = 8; off; off >>= 1) ss += __shfl_xor_sync(0xffffffffu, ss, off);
        float sc = sqrtf(ss) / (1.0f + ss);   // same across the 16-lane c-group
        vs4[tid] = make_float4(a.x * sc, a.y * sc, a.z * sc, a.w * sc);
    }
    __syncthreads();

    float4 p[8];
#pragma unroll
    for (int j = 0; j < 8; j++) p[j] = make_float4(0.f, 0.f, 0.f, 0.f);

    const int sbase = w8 * 64 + warp * 8;
    for (int si = 0; si < 8; si++) {
        const int s = sbase + si;
        const float4* __restrict__ up = (const float4*)(g_uhat + ((size_t)b * SS + s) * 1024);

        float4 u[8];
#pragma unroll
        for (int j = 0; j < 8; j++) u[j] = up[j * 32 + lane];

        // dots: d_c = sum_o u*v for c = 2j+hf; half-warp reduce per j
#pragma unroll
        for (int j = 0; j < 8; j++) {
            float4 v = vs4[(2 * j + hf) * 16 + l16];
            float d = u[j].x * v.x + u[j].y * v.y + u[j].z * v.z + u[j].w * v.w;
#pragma unroll
            for (int off = 8; off; off >>= 1) d += __shfl_xor_sync(0xffffffffu, d, off);
            if (l16 == 0) sdot[warp * 16 + 2 * j + hf] = d;
        }
        __syncwarp();

        // b_ij update + softmax (lanes 0..15)
        if (lane < 16) {
            float t = sdot[warp * 16 + lane];
            float* bp = g_b + ((size_t)b * SS + s) * CC;
            if (mode == 1) t += bp[lane];
            bp[lane] = t;
            float m = t;
#pragma unroll
            for (int off = 8; off; off >>= 1)
                m = fmaxf(m, __shfl_xor_sync(0xffffu, m, off));
            float e = __expf(t - m);
            float sum = e;
#pragma unroll
            for (int off = 8; off; off >>= 1)
                sum += __shfl_xor_sync(0xffffu, sum, off);
            sdot[warp * 16 + lane] = e / sum;      // c_ij
        }
        __syncwarp();

        // weighted accumulation (reuses u regs)
#pragma unroll
        for (int j = 0; j < 8; j++) {
            float w = sdot[warp * 16 + 2 * j + hf];   // broadcast within half
            p[j].x += w * u[j].x; p[j].y += w * u[j].y;
            p[j].z += w * u[j].z; p[j].w += w * u[j].w;
        }
    }

    // per-warp partials -> smem, then block reduce (deterministic)
#pragma unroll
    for (int j = 0; j < 8; j++) part4[warp * 256 + j * 32 + lane] = p[j];
    __syncthreads();

    float4 t = make_float4(0.f, 0.f, 0.f, 0.f);
#pragma unroll
    for (int w = 0; w < 8; w++) {
        float4 q = part4[w * 256 + tid];
        t.x += q.x; t.y += q.y; t.z += q.z; t.w += q.w;
    }
    g_sjp[mode][((size_t)w8 * BB + b) * 256 + tid] = t;
}

// ---------------------------------------------------------------------------
// finish: reduce buf1 slices -> s_j; squash -> d_out. grid B*C x 64.
// ---------------------------------------------------------------------------
__global__ void __launch_bounds__(64) finish_kernel(float* __restrict__ d_out) {
    __shared__ float sh[64];
    __shared__ float scl;
    const int bc = blockIdx.x;
    const int b  = bc >> 4;
    const int c  = bc & 15;
    const int o  = threadIdx.x;

    const float* base = (const float*)&g_sjp[1][0];
    float sjv = 0.f;
#pragma unroll
    for (int w = 0; w < 8; w++)
        sjv += base[((size_t)w * BB + b) * 1024 + c * 64 + o];

    sh[o] = sjv * sjv;
    __syncthreads();
    if (o < 32) {
        float t = sh[o] + sh[o + 32];
#pragma unroll
        for (int off = 16; off; off >>= 1) t += __shfl_xor_sync(0xffffffffu, t, off);
        if (o == 0) scl = sqrtf(t) / (1.0f + t);
    }
    __syncthreads();
    d_out[(size_t)bc * DOUT + o] = sjv * scl;
}

// ---------------------------------------------------------------------------
extern "C" void kernel_launch(void* const* d_in, const int* in_sizes, int n_in,
                              void* d_out, int out_size) {
    const float* x = (const float*)d_in[0];   // [B,S,din]
    const float* W = (const float*)d_in[1];   // [C,S,din,dout]
    float* out = (float*)d_out;               // [B,C,dout]

    const int gsm = 2 * 32 * XPAD * (int)sizeof(__nv_bfloat16)
                  + 2 * RINGSZ * (int)sizeof(float);   // 33792 + 43520 = 77312
    cudaFuncSetAttribute(gemm_uhat_kernel,
                         cudaFuncAttributeMaxDynamicSharedMemorySize, gsm);

    dim3 ggrid(SS, CC / 2);
    gemm_uhat_kernel<<<ggrid, 256, gsm>>>(x, W);

    r1_sj_kernel<<<BB * CC, 256>>>();         // it0: uniform -> v0
    fused_route_kernel<<<BB * 8, 256>>>(0);   // dots(v0); b=dot; softmax; s_j -> buf0
    fused_route_kernel<<<BB * 8, 256>>>(1);   // v1=squash(buf0); b+=dot; s_j -> buf1
    finish_kernel<<<BB * CC, 64>>>(out);      // v2=squash(buf1) -> out
}

// round 14
// speedup vs baseline: 1.3162x; 1.1797x over previous
#include <cuda_runtime.h>
#include <cuda_bf16.h>
#include <math.h>
#include <stdint.h>

#define BB   32
#define SS   512
#define CC   16
#define DIN  256
#define DOUT 64

#define XPAD 264       // bf16 row stride for Xs[b][k] (528B rows, ldmatrix conflict-free)
#define WSTRIDE 68     // fp32 row stride for W stage rows (bank = 8q+ar, conflict-free)
#define KSTAGE 16      // K rows per cp.async stage
#define NSTAGES 4
#define NCHUNK 16      // 256 / 16
#define RINGSZ (NSTAGES * KSTAGE * WSTRIDE)   // floats per capsule ring

// Scratch (allocation-free rule: __device__ globals)
__device__ float g_uhat[(size_t)BB * SS * CC * DOUT]; // 64 MiB, [b][s][c][o]
__device__ float g_b[(size_t)BB * SS * CC];           // b_ij [b][s][c]
__device__ float g_v[(size_t)BB * CC * DOUT];         // v_j  [b][c][o] (it0 only)
__device__ float4 g_sjp[2][(size_t)8 * BB * 256];     // s_j slices [buf][w8][b][(c,o)/4]

__device__ __forceinline__ uint32_t pack_bf2(float a, float b) {
    __nv_bfloat162 t = __floats2bfloat162_rn(a, b);
    return *reinterpret_cast<uint32_t*>(&t);
}

#define MMA_BF16(d, a, b)                                                     \
    asm volatile(                                                             \
        "mma.sync.aligned.m16n8k16.row.col.f32.bf16.bf16.f32 "                \
        "{%0,%1,%2,%3},{%4,%5,%6,%7},{%8,%9},{%0,%1,%2,%3};"                  \
        : "+f"(d[0]), "+f"(d[1]), "+f"(d[2]), "+f"(d[3])                      \
        : "r"(a[0]), "r"(a[1]), "r"(a[2]), "r"(a[3]), "r"(b[0]), "r"(b[1]))

#define LDSM_X4(r0, r1, r2, r3, addr)                                         \
    asm volatile("ldmatrix.sync.aligned.m8n8.x4.shared.b16 {%0,%1,%2,%3}, [%4];" \
                 : "=r"(r0), "=r"(r1), "=r"(r2), "=r"(r3) : "r"(addr))

// ---------------------------------------------------------------------------
// GEMM: u_hat[b,s,c,o] = sum_i x[b,s,i] * W[c,s,i,o]
// grid (S, C/2), 256 threads, 3 blocks/SM. TWO capsules (c, c+8) per block
// share one staged X tile; each 128-thread half streams its own W slab
// through a 4-stage cp.async ring (per-thread group accounting). Split-bf16
// (truncation) conversion fused into B-fragment build; A via ldmatrix.
// ---------------------------------------------------------------------------
__global__ void __launch_bounds__(256, 3) gemm_uhat_kernel(const float* __restrict__ x,
                                                           const float* __restrict__ W) {
    extern __shared__ char raw[];
    __nv_bfloat16* Xh = (__nv_bfloat16*)raw;                 // [32][XPAD]
    __nv_bfloat16* Xl = Xh + 32 * XPAD;
    float* Wring = (float*)(Xl + 32 * XPAD);                 // [2][NSTAGES][KSTAGE][WSTRIDE]

    const int s   = blockIdx.x;
    const int tid = threadIdx.x;
    const int cw  = tid >> 7;            // capsule half: 0 or 1
    const int wg  = tid & 127;           // tid within half
    const int cc  = blockIdx.y + cw * 8; // this half's capsule

    const float* Wp = W + ((size_t)cc * SS + s) * (size_t)(DIN * DOUT);
    float* myring = Wring + cw * RINGSZ;

    uint32_t ring_u32;
    {
        uint32_t tmp;
        asm("{ .reg .u64 t; cvta.to.shared.u64 t, %1; cvt.u32.u64 %0, t; }"
            : "=r"(tmp) : "l"((void*)myring));
        ring_u32 = tmp;
    }

    const int wrow = wg >> 4;           // 0..7 (rows wrow, wrow+8)
    const int wseg = wg & 15;           // 16B segment within 256B row
#define ISSUE_STAGE(slot, chunk)                                              \
    {                                                                         \
        const float* srcb = Wp + ((chunk) * KSTAGE) * DOUT + wseg * 4;        \
        uint32_t dstb = ring_u32 + (uint32_t)(slot) * (KSTAGE * WSTRIDE * 4)  \
                        + wseg * 16;                                          \
        asm volatile("cp.async.cg.shared.global [%0], [%1], 16;" ::           \
                     "r"(dstb + wrow * (WSTRIDE * 4)),                        \
                     "l"(srcb + wrow * DOUT) : "memory");                     \
        asm volatile("cp.async.cg.shared.global [%0], [%1], 16;" ::           \
                     "r"(dstb + (wrow + 8) * (WSTRIDE * 4)),                  \
                     "l"(srcb + (wrow + 8) * DOUT) : "memory");               \
        asm volatile("cp.async.commit_group;" ::: "memory");                  \
    }

    // prologue: chunks 0..2 in flight (3 groups per thread)
    ISSUE_STAGE(0, 0);
    ISSUE_STAGE(1, 1);
    ISSUE_STAGE(2, 2);

    // ---- stage X tile (32 x 256 fp32) as hi/lo bf16 (RN split), all 256 thr ----
    for (int i = tid; i < 2048; i += 256) {
        const int b = i >> 6;
        const int k = (i & 63) * 4;
        float4 f = ((const float4*)(x + ((size_t)b * SS + s) * DIN))[i & 63];
        float hx = __bfloat162float(__float2bfloat16(f.x));
        float hy = __bfloat162float(__float2bfloat16(f.y));
        float hz = __bfloat162float(__float2bfloat16(f.z));
        float hw = __bfloat162float(__float2bfloat16(f.w));
        *(uint32_t*)(Xh + b * XPAD + k)     = pack_bf2(f.x, f.y);
        *(uint32_t*)(Xh + b * XPAD + k + 2) = pack_bf2(f.z, f.w);
        *(uint32_t*)(Xl + b * XPAD + k)     = pack_bf2(f.x - hx, f.y - hy);
        *(uint32_t*)(Xl + b * XPAD + k + 2) = pack_bf2(f.z - hz, f.w - hw);
    }

    const int lane = tid & 31;
    const int w4   = (tid >> 5) & 3;     // warp within half
    const int nb   = w4 * 16;
    const int ar   = lane >> 2;          // 0..7
    const int kq   = (lane & 3) * 2;     // 0,2,4,6

    const int arow = lane & 15;
    const int akof = (lane >> 4) * 8;
    uint32_t xh_u32, xl_u32;
    {
        uint32_t t0, t1;
        asm("{ .reg .u64 t; cvta.to.shared.u64 t, %1; cvt.u32.u64 %0, t; }"
            : "=r"(t0) : "l"((void*)Xh));
        asm("{ .reg .u64 t; cvta.to.shared.u64 t, %1; cvt.u32.u64 %0, t; }"
            : "=r"(t1) : "l"((void*)Xl));
        xh_u32 = t0; xl_u32 = t1;
    }
    const uint32_t aoff0 = (uint32_t)((arow * XPAD + akof) * 2);
    const uint32_t aoff1 = (uint32_t)(((arow + 16) * XPAD + akof) * 2);

    float acc[2][2][4];
#pragma unroll
    for (int mt = 0; mt < 2; mt++)
#pragma unroll
        for (int nt = 0; nt < 2; nt++)
#pragma unroll
            for (int r = 0; r < 4; r++) acc[mt][nt][r] = 0.f;

    int slot_c = 0;   // consume slot
    int slot_p = 3;   // produce slot
#pragma unroll 4
    for (int ch = 0; ch < NCHUNK; ch++) {
        // per-thread committed groups = 3 + ch; <=2 pending => chunks 0..ch landed
        asm volatile("cp.async.wait_group 2;" ::: "memory");
        __syncthreads();   // RAW + WAR across both halves

        if (ch + 3 < NCHUNK) {
            ISSUE_STAGE(slot_p, ch + 3);
        } else {
            asm volatile("cp.async.commit_group;" ::: "memory");
        }
        if (++slot_p == NSTAGES) slot_p = 0;

        const float* Wst = myring + slot_c * (KSTAGE * WSTRIDE);
        if (++slot_c == NSTAGES) slot_c = 0;

        const int k0 = ch * KSTAGE;   // global k for X

        uint32_t ah[2][4], al[2][4];
        LDSM_X4(ah[0][0], ah[0][1], ah[0][2], ah[0][3], xh_u32 + aoff0 + k0 * 2);
        LDSM_X4(ah[1][0], ah[1][1], ah[1][2], ah[1][3], xh_u32 + aoff1 + k0 * 2);
        LDSM_X4(al[0][0], al[0][1], al[0][2], al[0][3], xl_u32 + aoff0 + k0 * 2);
        LDSM_X4(al[1][0], al[1][1], al[1][2], al[1][3], xl_u32 + aoff1 + k0 * 2);

        uint32_t bh[2][2], bl[2][2];
#pragma unroll
        for (int nt = 0; nt < 2; nt++) {
            const int n = nb + nt * 8 + ar;
#pragma unroll
            for (int kg = 0; kg < 2; kg++) {
                const int krow = kq + kg * 8;
                float w0 = Wst[krow * WSTRIDE + n];
                float w1 = Wst[(krow + 1) * WSTRIDE + n];
                uint32_t u0 = __float_as_uint(w0);
                uint32_t u1 = __float_as_uint(w1);
                uint32_t hp;
                asm("prmt.b32 %0, %1, %2, 0x7632;" : "=r"(hp) : "r"(u0), "r"(u1));
                float l0 = w0 - __uint_as_float(u0 & 0xffff0000u);
                float l1 = w1 - __uint_as_float(u1 & 0xffff0000u);
                bh[nt][kg] = hp;
                bl[nt][kg] = pack_bf2(l0, l1);
            }
        }

#pragma unroll
        for (int mt = 0; mt < 2; mt++)
#pragma unroll
            for (int nt = 0; nt < 2; nt++) {
                MMA_BF16(acc[mt][nt], ah[mt], bh[nt]);
                MMA_BF16(acc[mt][nt], ah[mt], bl[nt]);
                MMA_BF16(acc[mt][nt], al[mt], bh[nt]);
            }
    }

    // ---- store: u_hat[b][s][c][o] ----
#pragma unroll
    for (int mt = 0; mt < 2; mt++) {
        const int row = ar + mt * 16;
#pragma unroll
        for (int nt = 0; nt < 2; nt++) {
            const int o = nb + nt * 8 + kq;
            float* p0 = g_uhat + (((size_t)row * SS + s) * CC + cc) * DOUT + o;
            float* p1 = g_uhat + (((size_t)(row + 8) * SS + s) * CC + cc) * DOUT + o;
            *(float2*)p0 = make_float2(acc[mt][nt][0], acc[mt][nt][1]);
            *(float2*)p1 = make_float2(acc[mt][nt][2], acc[mt][nt][3]);
        }
    }
}

// ---------------------------------------------------------------------------
// R1 (it0): s_j = (1/16) * sum_s u_hat[b,s,c,:] -> squash -> g_v.
// ---------------------------------------------------------------------------
__global__ void __launch_bounds__(256) r1_sj_kernel(void) {
    __shared__ float4 red4[256];
    __shared__ float sj[64];
    __shared__ float scl;

    const int bc  = blockIdx.x;
    const int b   = bc >> 4;
    const int c   = bc & 15;
    const int tid = threadIdx.x;

    const int col = tid & 15;
    const int sg  = tid >> 4;
    const float4* __restrict__ up4 = (const float4*)g_uhat;
    const size_t base = (size_t)b * SS * 256 + (size_t)c * 16;

    float4 acc = make_float4(0.f, 0.f, 0.f, 0.f);
#pragma unroll 8
    for (int s = sg; s < SS; s += 16) {
        float4 u = up4[base + (size_t)s * 256 + col];
        acc.x += u.x; acc.y += u.y; acc.z += u.z; acc.w += u.w;
    }
    acc.x *= (1.f/16.f); acc.y *= (1.f/16.f); acc.z *= (1.f/16.f); acc.w *= (1.f/16.f);
    red4[tid] = acc;
    __syncthreads();

    if (tid < 64) {
        const int cl = tid >> 2;
        const int cp = tid & 3;
        float t = 0.f;
#pragma unroll
        for (int g = 0; g < 16; g++) {
            float4 v = red4[g * 16 + cl];
            t += (cp == 0) ? v.x : (cp == 1) ? v.y : (cp == 2) ? v.z : v.w;
        }
        sj[tid] = t;
    }
    __syncthreads();

    if (tid < 32) {
        float t = sj[tid] * sj[tid] + sj[tid + 32] * sj[tid + 32];
#pragma unroll
        for (int off = 16; off; off >>= 1) t += __shfl_xor_sync(0xffffffffu, t, off);
        if (tid == 0) scl = sqrtf(t) / (1.0f + t);
    }
    __syncthreads();
    if (tid < 64)
        g_v[(size_t)bc * DOUT + tid] = sj[tid] * scl;
}

// ---------------------------------------------------------------------------
// F: fused (v-build) + agreement + b_ij + softmax + weighted partial s_j.
// 256 threads (8 warps), warp per s, 8 s per warp, 8 windows of 64 s.
// R10 config: register accumulators (89 regs, best measured).
// mode 0: v from g_v, b_ij = dot, slices -> buf0
// mode 1: v from reduce(buf0)+squash, b_ij += dot, slices -> buf1
// ---------------------------------------------------------------------------
__global__ void __launch_bounds__(256) fused_route_kernel(int mode) {
    __shared__ float4 vs4[256];       // v[b] as (c,o)/4
    __shared__ float4 part4[8 * 256]; // per-warp partial s_j
    __shared__ float  sdot[8 * 16];   // per-warp dots / c_ij

    const int b    = blockIdx.x >> 3;
    const int w8   = blockIdx.x & 7;
    const int tid  = threadIdx.x;
    const int warp = tid >> 5;
    const int lane = tid & 31;
    const int hf   = lane >> 4;       // capsule parity
    const int l16  = lane & 15;

    // ---- build v in smem ----
    if (mode == 0) {
        vs4[tid] = ((const float4*)(g_v + (size_t)b * CC * DOUT))[tid];
    } else {
        float4 a = make_float4(0.f, 0.f, 0.f, 0.f);
#pragma unroll
        for (int w = 0; w < 8; w++) {
            float4 t = g_sjp[0][((size_t)w * BB + b) * 256 + tid];
            a.x += t.x; a.y += t.y; a.z += t.z; a.w += t.w;
        }
        float ss = a.x * a.x + a.y * a.y + a.z * a.z + a.w * a.w;
#pragma unroll
        for (int off = 8; off; off >>= 1) ss += __shfl_xor_sync(0xffffffffu, ss, off);
        float sc = sqrtf(ss) / (1.0f + ss);   // same across the 16-lane c-group
        vs4[tid] = make_float4(a.x * sc, a.y * sc, a.z * sc, a.w * sc);
    }
    __syncthreads();

    float4 p[8];
#pragma unroll
    for (int j = 0; j < 8; j++) p[j] = make_float4(0.f, 0.f, 0.f, 0.f);

    const int sbase = w8 * 64 + warp * 8;
    for (int si = 0; si < 8; si++) {
        const int s = sbase + si;
        const float4* __restrict__ up = (const float4*)(g_uhat + ((size_t)b * SS + s) * 1024);

        float4 u[8];
#pragma unroll
        for (int j = 0; j < 8; j++) u[j] = up[j * 32 + lane];

        // dots: d_c = sum_o u*v for c = 2j+hf; half-warp reduce per j
#pragma unroll
        for (int j = 0; j < 8; j++) {
            float4 v = vs4[(2 * j + hf) * 16 + l16];
            float d = u[j].x * v.x + u[j].y * v.y + u[j].z * v.z + u[j].w * v.w;
#pragma unroll
            for (int off = 8; off; off >>= 1) d += __shfl_xor_sync(0xffffffffu, d, off);
            if (l16 == 0) sdot[warp * 16 + 2 * j + hf] = d;
        }
        __syncwarp();

        // b_ij update + softmax (lanes 0..15)
        if (lane < 16) {
            float t = sdot[warp * 16 + lane];
            float* bp = g_b + ((size_t)b * SS + s) * CC;
            if (mode == 1) t += bp[lane];
            bp[lane] = t;
            float m = t;
#pragma unroll
            for (int off = 8; off; off >>= 1)
                m = fmaxf(m, __shfl_xor_sync(0xffffu, m, off));
            float e = __expf(t - m);
            float sum = e;
#pragma unroll
            for (int off = 8; off; off >>= 1)
                sum += __shfl_xor_sync(0xffffu, sum, off);
            sdot[warp * 16 + lane] = e / sum;      // c_ij
        }
        __syncwarp();

        // weighted accumulation (reuses u regs)
#pragma unroll
        for (int j = 0; j < 8; j++) {
            float w = sdot[warp * 16 + 2 * j + hf];   // broadcast within half
            p[j].x += w * u[j].x; p[j].y += w * u[j].y;
            p[j].z += w * u[j].z; p[j].w += w * u[j].w;
        }
    }

    // per-warp partials -> smem, then block reduce (deterministic)
#pragma unroll
    for (int j = 0; j < 8; j++) part4[warp * 256 + j * 32 + lane] = p[j];
    __syncthreads();

    float4 t = make_float4(0.f, 0.f, 0.f, 0.f);
#pragma unroll
    for (int w = 0; w < 8; w++) {
        float4 q = part4[w * 256 + tid];
        t.x += q.x; t.y += q.y; t.z += q.z; t.w += q.w;
    }
    g_sjp[mode][((size_t)w8 * BB + b) * 256 + tid] = t;
}

// ---------------------------------------------------------------------------
// finish: reduce buf1 slices -> s_j; squash -> d_out. grid B*C x 64.
// ---------------------------------------------------------------------------
__global__ void __launch_bounds__(64) finish_kernel(float* __restrict__ d_out) {
    __shared__ float sh[64];
    __shared__ float scl;
    const int bc = blockIdx.x;
    const int b  = bc >> 4;
    const int c  = bc & 15;
    const int o  = threadIdx.x;

    const float* base = (const float*)&g_sjp[1][0];
    float sjv = 0.f;
#pragma unroll
    for (int w = 0; w < 8; w++)
        sjv += base[((size_t)w * BB + b) * 1024 + c * 64 + o];

    sh[o] = sjv * sjv;
    __syncthreads();
    if (o < 32) {
        float t = sh[o] + sh[o + 32];
#pragma unroll
        for (int off = 16; off; off >>= 1) t += __shfl_xor_sync(0xffffffffu, t, off);
        if (o == 0) scl = sqrtf(t) / (1.0f + t);
    }
    __syncthreads();
    d_out[(size_t)bc * DOUT + o] = sjv * scl;
}

// ---------------------------------------------------------------------------
extern "C" void kernel_launch(void* const* d_in, const int* in_sizes, int n_in,
                              void* d_out, int out_size) {
    const float* x = (const float*)d_in[0];   // [B,S,din]
    const float* W = (const float*)d_in[1];   // [C,S,din,dout]
    float* out = (float*)d_out;               // [B,C,dout]

    const int gsm = 2 * 32 * XPAD * (int)sizeof(__nv_bfloat16)
                  + 2 * RINGSZ * (int)sizeof(float);   // 33792 + 34816 = 68608
    cudaFuncSetAttribute(gemm_uhat_kernel,
                         cudaFuncAttributeMaxDynamicSharedMemorySize, gsm);

    dim3 ggrid(SS, CC / 2);
    gemm_uhat_kernel<<<ggrid, 256, gsm>>>(x, W);

    r1_sj_kernel<<<BB * CC, 256>>>();         // it0: uniform -> v0
    fused_route_kernel<<<BB * 8, 256>>>(0);   // dots(v0); b=dot; softmax; s_j -> buf0
    fused_route_kernel<<<BB * 8, 256>>>(1);   // v1=squash(buf0); b+=dot; s_j -> buf1
    finish_kernel<<<BB * CC, 64>>>(out);      // v2=squash(buf1) -> out
}